// round 10
// baseline (speedup 1.0000x reference)
#include <cuda_runtime.h>
#include <cstdint>

#define NB 1024
#define NL 4096
#define RPC 4                 // rows per CTA
#define NCTA (NB / RPC)       // 256
#define NT 512
#define NWARP (NT / 32)       // 16
#define ROW_BYTES (NL * 4)    // 16 KB
#define STAGE_BYTES (2 * ROW_BYTES)   // lab + prob = 32 KB
#define NSTAGE 2
// 2*log2(e)/tau and ln(2)
#define K2F  3.3945765667975607f
#define LN2F 0.6931471805599453f

__device__ float g_row[NB];
__device__ unsigned g_count = 0;   // self-resetting via atomicInc wraparound

__device__ __forceinline__ float ex2f(float x) {
    float r;
    asm("ex2.approx.f32 %0, %1;" : "=f"(r) : "f"(x));
    return r;
}
__device__ __forceinline__ uint32_t smem_u32(const void* p) {
    return (uint32_t)__cvta_generic_to_shared(p);
}
__device__ __forceinline__ void mbar_init(uint32_t mbar, uint32_t cnt) {
    asm volatile("mbarrier.init.shared.b64 [%0], %1;" :: "r"(mbar), "r"(cnt) : "memory");
}
__device__ __forceinline__ void mbar_expect_tx(uint32_t mbar, uint32_t bytes) {
    asm volatile("mbarrier.arrive.expect_tx.shared.b64 _, [%0], %1;" :: "r"(mbar), "r"(bytes) : "memory");
}
__device__ __forceinline__ void bulk_g2s(uint32_t dst, const void* src, uint32_t bytes, uint32_t mbar) {
    asm volatile("cp.async.bulk.shared::cta.global.mbarrier::complete_tx::bytes [%0], [%1], %2, [%3];"
                 :: "r"(dst), "l"(src), "r"(bytes), "r"(mbar) : "memory");
}
__device__ __forceinline__ void mbar_wait(uint32_t mbar, uint32_t phase) {
    uint32_t done;
    do {
        asm volatile("{\n\t.reg .pred p;\n\t"
                     "mbarrier.try_wait.parity.acquire.cta.shared::cta.b64 p, [%1], %2, 0x989680;\n\t"
                     "selp.b32 %0, 1, 0, p;\n\t}"
                     : "=r"(done) : "r"(mbar), "r"(phase) : "memory");
    } while (!done);
}

__global__ __launch_bounds__(NT)
void fused_kernel(const float* __restrict__ probs, const int* __restrict__ labels,
                  float* __restrict__ d_out) {
    extern __shared__ char dyn_smem[];   // NSTAGE stages of [lab 16K | prob 16K]
    __shared__ alignas(8) unsigned long long s_mbar[NSTAGE];
    __shared__ int   ws[2 * NWARP];      // 32 chunk partials, global order k*16+w
    __shared__ int   woff[2 * NWARP + 1];
    __shared__ float sS[NWARP], sW[NWARP];
    __shared__ int   s_last;

    const int bid  = blockIdx.x;
    const int t    = threadIdx.x;
    const int lane = t & 31;
    const int warp = t >> 5;
    const int row0 = bid * RPC;

    uint32_t mb[NSTAGE];
#pragma unroll
    for (int i = 0; i < NSTAGE; i++) mb[i] = smem_u32(&s_mbar[i]);

    if (t == 0) {
#pragma unroll
        for (int i = 0; i < NSTAGE; i++) mbar_init(mb[i], 1);
        asm volatile("fence.proxy.async.shared::cta;" ::: "memory");
    }
    __syncthreads();

    // Prime the ring: rows 0 and 1.
    if (t == 0) {
#pragma unroll
        for (int s = 0; s < NSTAGE; s++) {
            const size_t roff = (size_t)(row0 + s) * NL;
            mbar_expect_tx(mb[s], STAGE_BYTES);
            bulk_g2s(smem_u32(dyn_smem) + s * STAGE_BYTES,             labels + roff, ROW_BYTES, mb[s]);
            bulk_g2s(smem_u32(dyn_smem) + s * STAGE_BYTES + ROW_BYTES, probs  + roff, ROW_BYTES, mb[s]);
        }
    }

#pragma unroll
    for (int r = 0; r < RPC; r++) {
        const int   stage = r & (NSTAGE - 1);
        const uint32_t ph = (r >> 1) & 1;
        char* sbase = dyn_smem + stage * STAGE_BYTES;

        // ---- wait operands of row r ----
        mbar_wait(mb[stage], ph);

        const int4*   lab4 = reinterpret_cast<const int4*>(sbase);
        const float4* pr4  = reinterpret_cast<const float4*>(sbase + ROW_BYTES);
        int4   a0 = lab4[t];          // elements 4t..4t+3        (chunk 0)
        int4   a1 = lab4[NT + t];     // elements 2048+4t..4t+3   (chunk 1)
        float4 p0 = pr4[t];
        float4 p1 = pr4[NT + t];

        // All operands now in registers; free this stage for row r+2.
        __syncthreads();
        if (t == 0 && r + NSTAGE < RPC) {
            const size_t roff = (size_t)(row0 + r + NSTAGE) * NL;
            mbar_expect_tx(mb[stage], STAGE_BYTES);
            bulk_g2s(smem_u32(sbase),             labels + roff, ROW_BYTES, mb[stage]);
            bulk_g2s(smem_u32(sbase) + ROW_BYTES, probs  + roff, ROW_BYTES, mb[stage]);
        }

        // ---- block scan of label sums (TMA for r+2 streams underneath) ----
        int s0 = a0.x + a0.y + a0.z + a0.w;
        int s1 = a1.x + a1.y + a1.z + a1.w;
        int inc0 = s0, inc1 = s1;
#pragma unroll
        for (int d = 1; d < 32; d <<= 1) {
            int n0 = __shfl_up_sync(0xffffffffu, inc0, d);
            int n1 = __shfl_up_sync(0xffffffffu, inc1, d);
            if (lane >= d) { inc0 += n0; inc1 += n1; }
        }
        if (lane == 31) { ws[warp] = inc0; ws[NWARP + warp] = inc1; }
        __syncthreads();
        if (warp == 0) {                      // scan 32 chunk partials in global order
            int val = ws[lane];
            int inc = val;
#pragma unroll
            for (int d = 1; d < 32; d <<= 1) {
                int n = __shfl_up_sync(0xffffffffu, inc, d);
                if (lane >= d) inc += n;
            }
            woff[lane] = inc - val;           // exclusive
            if (lane == 31) woff[32] = inc;   // T
        }
        __syncthreads();

        const int T    = woff[32];
        const int pre0 = woff[warp] + (inc0 - s0);
        const int pre1 = woff[NWARP + warp] + (inc1 - s1);

        // ---- per-element math ----
        float S = 0.0f, W = 0.0f;             // W in log2 units
#pragma unroll
        for (int k = 0; k < 2; k++) {
            const int4   a = (k == 0) ? a0 : a1;
            const float4 p = (k == 0) ? p0 : p1;
            const int kbase = k * (NL / 2) + 4 * t + 1 + T;
            const float r0  = __fdividef(1.0f, (float)kbase);   // one MUFU.RCP per chunk
            float kr[4];
            kr[0] = K2F * r0;                                   // folds 2*log2(e)/tau
#pragma unroll
            for (int j = 1; j < 4; j++) {
                const float tj = (float)j * r0;
                kr[j] = kr[0] * __fmaf_rn(tj, tj, 1.0f - tj);   // 1/(kbase+j) Taylor
            }
            float cf = (float)((k == 0) ? pre0 : pre1);
            const int   v[4] = {a.x, a.y, a.z, a.w};
            const float q[4] = {p.x, p.y, p.z, p.w};
#pragma unroll
            for (int j = 0; j < 4; j++) {
                cf += v[j] ? 1.0f : 0.0f;
                const float f  = cf * kr[j];                    // (r/tau)*log2e; 0 when c==0
                const float e  = ex2f(f);
                const float df = f - __log2f(q[j]);
                S += e;
                W = __fmaf_rn(e, df, W);
            }
        }

        // ---- block reduce (S, W) ----
#pragma unroll
        for (int d = 16; d; d >>= 1) {
            S += __shfl_down_sync(0xffffffffu, S, d);
            W += __shfl_down_sync(0xffffffffu, W, d);
        }
        if (lane == 0) { sS[warp] = S; sW[warp] = W; }
        __syncthreads();
        if (t == 0) {
            float St = 0.0f, Wt = 0.0f;
#pragma unroll
            for (int w = 0; w < NWARP; w++) { St += sS[w]; Wt += sW[w]; }
            g_row[row0 + r] = LN2F * (Wt / St) - __logf(St);    // ln2*(W/S) - ln(S)
        }
        __syncthreads();   // protect ws/woff/sS/sW reuse next row
    }

    // ---- completion ticket; last CTA reduces all rows deterministically ----
    if (t == 0) {
        __threadfence();
        unsigned ticket = atomicInc(&g_count, NCTA - 1);        // wraps after NCTA
        s_last = (ticket == NCTA - 1);
    }
    __syncthreads();

    if (s_last) {
        __threadfence();
        const volatile float* gr = g_row;
        float acc = 0.0f;
#pragma unroll
        for (int i = 0; i < NB / NT; i++) acc += gr[t + i * NT];
#pragma unroll
        for (int d = 16; d; d >>= 1) acc += __shfl_down_sync(0xffffffffu, acc, d);
        __shared__ float sm2[NWARP];
        if (lane == 0) sm2[warp] = acc;
        __syncthreads();
        if (t == 0) {
            float tot = 0.0f;
#pragma unroll
            for (int w = 0; w < NWARP; w++) tot += sm2[w];
            d_out[0] = tot * (1.0f / (float)NB);
        }
    }
}

extern "C" void kernel_launch(void* const* d_in, const int* in_sizes, int n_in,
                              void* d_out, int out_size) {
    const float* probs  = (const float*)d_in[0];   // output: (B, L, 1) f32
    const int*   labels = (const int*)d_in[1];     // labels: (B, L) i32
    static int configured = 0;
    if (!configured) {
        cudaFuncSetAttribute(fused_kernel, cudaFuncAttributeMaxDynamicSharedMemorySize,
                             NSTAGE * STAGE_BYTES);
        configured = 1;
    }
    fused_kernel<<<NCTA, NT, NSTAGE * STAGE_BYTES>>>(probs, labels, (float*)d_out);
}

// round 11
// speedup vs baseline: 1.1544x; 1.1544x over previous
#include <cuda_runtime.h>
#include <cstdint>

#define NB 1024
#define NL 4096
#define NT 512
#define NWG 4                 // warpgroups per CTA = rows per CTA
#define NCTA (NB / NWG)       // 256
#define NCHUNK 8              // 8 chunks of 128 elems per warp (4 per lane per chunk)
// 2*log2(e)/tau and ln(2)
#define K2F  3.3945765667975607f
#define LN2F 0.6931471805599453f

__device__ float g_row[NB];
__device__ unsigned g_count = 0;   // self-resetting via atomicInc wraparound

__device__ __forceinline__ float ex2f(float x) {
    float r;
    asm("ex2.approx.f32 %0, %1;" : "=f"(r) : "f"(x));
    return r;
}

__global__ __launch_bounds__(NT, 2)
void fused_kernel(const float* __restrict__ probs, const int* __restrict__ labels,
                  float* __restrict__ d_out) {
    __shared__ int   s_wtot[NT / 32];        // per-warp label totals
    __shared__ float s_S[NT / 32], s_W[NT / 32];
    __shared__ int   s_last;

    const int t    = threadIdx.x;
    const int lane = t & 31;
    const int warp = t >> 5;        // 0..15
    const int wg   = warp >> 2;     // 0..3  (row within CTA)
    const int wwin = warp & 3;      // warp within warpgroup
    const int row  = blockIdx.x * NWG + wg;
    const int barid = 1 + wg;       // named barrier per warpgroup

    const size_t roff  = (size_t)row * NL;
    const int    wbase = wwin * 1024;             // warp's contiguous 1024-elem block
    const int4*   lab4 = reinterpret_cast<const int4*>(labels + roff + wbase);
    const float4* pr4  = reinterpret_cast<const float4*>(probs  + roff + wbase);
    // chunk k, lane l covers elements wbase + k*128 + 4l .. 4l+3  (vector idx k*32+l)

    // ---- issue first prob loads early (independent of labels) ----
    float4 pst[4];
#pragma unroll
    for (int k = 0; k < 4; k++) pst[k] = pr4[k * 32 + lane];

    // ---- pass 1: labels -> bitpack + prefix via ballot/popc (no scans, no block bar) ----
    unsigned bits = 0;
    int cfstart[NCHUNK];            // exclusive count before (k, lane, 0), relative to warp
    int running = 0;
    const unsigned lt = (1u << lane) - 1u;
#pragma unroll
    for (int k = 0; k < NCHUNK; k++) {
        int4 a = lab4[k * 32 + lane];
        unsigned m0 = __ballot_sync(0xffffffffu, a.x);
        unsigned m1 = __ballot_sync(0xffffffffu, a.y);
        unsigned m2 = __ballot_sync(0xffffffffu, a.z);
        unsigned m3 = __ballot_sync(0xffffffffu, a.w);
        cfstart[k] = running + __popc(m0 & lt) + __popc(m1 & lt)
                             + __popc(m2 & lt) + __popc(m3 & lt);
        bits |= (unsigned)(a.x & 1) << (4 * k)
              | (unsigned)(a.y & 1) << (4 * k + 1)
              | (unsigned)(a.z & 1) << (4 * k + 2)
              | (unsigned)(a.w & 1) << (4 * k + 3);
        running += __popc(m0) + __popc(m1) + __popc(m2) + __popc(m3);
    }

    // ---- cross-warp totals within the warpgroup (one named barrier) ----
    if (lane == 0) s_wtot[warp] = running;
    asm volatile("bar.sync %0, %1;" :: "r"(barid), "r"(128) : "memory");
    const int w0 = s_wtot[wg * 4 + 0], w1 = s_wtot[wg * 4 + 1];
    const int w2 = s_wtot[wg * 4 + 2], w3 = s_wtot[wg * 4 + 3];
    const int T  = w0 + w1 + w2 + w3;
    int wgb = 0;
    if (wwin > 0) wgb += w0;
    if (wwin > 1) wgb += w1;
    if (wwin > 2) wgb += w2;

    // ---- pass 2: per-element math, prob loads pipelined 4 deep ----
    float S = 0.0f, W = 0.0f;       // W in log2 units
#pragma unroll
    for (int k = 0; k < NCHUNK; k++) {
        const float4 p = pst[k & 3];
        if (k + 4 < NCHUNK) pst[k & 3] = pr4[(k + 4) * 32 + lane];

        const int   kb = wbase + k * 128 + 4 * lane + 1 + T;   // k_idx + T, >= T+1
        const float r0 = __fdividef(1.0f, (float)kb);          // one MUFU.RCP / 4 elems
        float kr[4];
        kr[0] = K2F * r0;                                      // folds 2*log2(e)/tau
#pragma unroll
        for (int j = 1; j < 4; j++) {
            const float tj = (float)j * r0;                    // 1/(kb+j) ~ r0*(1-t+t^2)
            kr[j] = kr[0] * __fmaf_rn(tj, tj, 1.0f - tj);
        }
        float cf = (float)(wgb + cfstart[k]);
        const float q[4] = {p.x, p.y, p.z, p.w};
#pragma unroll
        for (int j = 0; j < 4; j++) {
            const unsigned b = (bits >> (4 * k + j)) & 1u;
            cf += b ? 1.0f : 0.0f;
            const float f  = cf * kr[j];                       // (r/tau)*log2e; 0 when c==0
            const float e  = ex2f(f);
            const float df = f - __log2f(q[j]);
            S += e;
            W = __fmaf_rn(e, df, W);
        }
    }

    // ---- warpgroup reduce (S, W): shfl within warp, smem across 4 warps ----
#pragma unroll
    for (int d = 16; d; d >>= 1) {
        S += __shfl_down_sync(0xffffffffu, S, d);
        W += __shfl_down_sync(0xffffffffu, W, d);
    }
    if (lane == 0) { s_S[warp] = S; s_W[warp] = W; }
    asm volatile("bar.sync %0, %1;" :: "r"(barid), "r"(128) : "memory");
    if (wwin == 0 && lane == 0) {
        const float St = s_S[wg * 4 + 0] + s_S[wg * 4 + 1] + s_S[wg * 4 + 2] + s_S[wg * 4 + 3];
        const float Wt = s_W[wg * 4 + 0] + s_W[wg * 4 + 1] + s_W[wg * 4 + 2] + s_W[wg * 4 + 3];
        g_row[row] = LN2F * (Wt / St) - __logf(St);            // ln2*(W/S) - ln(S)
        __threadfence();                                       // writer publishes its row
    }

    // ---- completion ticket; last CTA reduces all rows deterministically ----
    __syncthreads();
    if (t == 0) {
        unsigned ticket = atomicInc(&g_count, NCTA - 1);       // wraps after NCTA
        s_last = (ticket == NCTA - 1);
    }
    __syncthreads();

    if (s_last) {
        __threadfence();
        const volatile float* gr = g_row;
        float acc = 0.0f;
#pragma unroll
        for (int i = 0; i < NB / NT; i++) acc += gr[t + i * NT];
#pragma unroll
        for (int d = 16; d; d >>= 1) acc += __shfl_down_sync(0xffffffffu, acc, d);
        __shared__ float sm2[NT / 32];
        if (lane == 0) sm2[warp] = acc;
        __syncthreads();
        if (t == 0) {
            float tot = 0.0f;
#pragma unroll
            for (int w = 0; w < NT / 32; w++) tot += sm2[w];
            d_out[0] = tot * (1.0f / (float)NB);
        }
    }
}

extern "C" void kernel_launch(void* const* d_in, const int* in_sizes, int n_in,
                              void* d_out, int out_size) {
    const float* probs  = (const float*)d_in[0];   // output: (B, L, 1) f32
    const int*   labels = (const int*)d_in[1];     // labels: (B, L) i32
    fused_kernel<<<NCTA, NT>>>(probs, labels, (float*)d_out);
}

// round 12
// speedup vs baseline: 1.2202x; 1.0570x over previous
#include <cuda_runtime.h>
#include <cstdint>

#define NB 1024
#define NL 4096
#define NT 512
#define GRID 296              // 2 CTAs per SM exactly (148 SMs)
#define NCHUNK 8              // 8 chunks of 128 elems per warp
// 2*log2(e)/tau and ln(2)
#define K2F  3.3945765667975607f
#define LN2F 0.6931471805599453f
#define FIXSCALE 4294967296.0   // 2^32

__device__ unsigned long long g_acc = 0;   // fixed-point sum, self-resetting
__device__ unsigned g_count = 0;           // ticket, self-resetting via atomicInc wrap

__device__ __forceinline__ float ex2f(float x) {
    float r;
    asm("ex2.approx.f32 %0, %1;" : "=f"(r) : "f"(x));
    return r;
}

__global__ __launch_bounds__(NT, 2)
void fused_kernel(const float* __restrict__ probs, const int* __restrict__ labels,
                  float* __restrict__ d_out) {
    __shared__ int   s_wtot[NT / 32];        // per-warp label totals
    __shared__ float s_S[NT / 32], s_W[NT / 32];

    const int t    = threadIdx.x;
    const int lane = t & 31;
    const int warp = t >> 5;        // 0..15
    const int wg   = warp >> 2;     // warpgroup 0..3
    const int wwin = warp & 3;      // warp within warpgroup
    const int barid = 1 + wg;

    // Transposed row map: wg 0..2 busy in ALL CTAs; only wg3 partially idle.
    // => max 7 busy warpgroups per SM (vs 8 with blocked mapping).
    const int row = wg * GRID + blockIdx.x;

    if (row < NB) {
        const size_t roff  = (size_t)row * NL;
        const int    wbase = wwin * 1024;             // warp's contiguous 1024-elem block
        const int4*   lab4 = reinterpret_cast<const int4*>(labels + roff + wbase);
        const float4* pr4  = reinterpret_cast<const float4*>(probs  + roff + wbase);
        // chunk k, lane l covers elements wbase + k*128 + 4l..4l+3

        // ---- early prob loads (independent of labels) ----
        float4 pst[4];
#pragma unroll
        for (int k = 0; k < 4; k++) pst[k] = pr4[k * 32 + lane];

        // ---- pass 1: labels -> bitpack + prefix via ballot/popc ----
        unsigned bits = 0;
        int cfstart[NCHUNK];        // exclusive count before (k, lane, 0), warp-relative
        int running = 0;
        const unsigned lt = (1u << lane) - 1u;
#pragma unroll
        for (int k = 0; k < NCHUNK; k++) {
            int4 a = lab4[k * 32 + lane];
            unsigned m0 = __ballot_sync(0xffffffffu, a.x);
            unsigned m1 = __ballot_sync(0xffffffffu, a.y);
            unsigned m2 = __ballot_sync(0xffffffffu, a.z);
            unsigned m3 = __ballot_sync(0xffffffffu, a.w);
            cfstart[k] = running + __popc(m0 & lt) + __popc(m1 & lt)
                                 + __popc(m2 & lt) + __popc(m3 & lt);
            bits |= (unsigned)(a.x & 1) << (4 * k)
                  | (unsigned)(a.y & 1) << (4 * k + 1)
                  | (unsigned)(a.z & 1) << (4 * k + 2)
                  | (unsigned)(a.w & 1) << (4 * k + 3);
            running += __popc(m0) + __popc(m1) + __popc(m2) + __popc(m3);
        }

        // ---- cross-warp totals within warpgroup (named barrier, 128 threads) ----
        if (lane == 0) s_wtot[warp] = running;
        asm volatile("bar.sync %0, %1;" :: "r"(barid), "r"(128) : "memory");
        const int w0 = s_wtot[wg * 4 + 0], w1 = s_wtot[wg * 4 + 1];
        const int w2 = s_wtot[wg * 4 + 2], w3 = s_wtot[wg * 4 + 3];
        const int T  = w0 + w1 + w2 + w3;
        int wgb = 0;
        if (wwin > 0) wgb += w0;
        if (wwin > 1) wgb += w1;
        if (wwin > 2) wgb += w2;

        // ---- pass 2: per-element math, prob loads pipelined 4 deep ----
        float S = 0.0f, W = 0.0f;   // W in log2 units
#pragma unroll
        for (int k = 0; k < NCHUNK; k++) {
            const float4 p = pst[k & 3];
            if (k + 4 < NCHUNK) pst[k & 3] = pr4[(k + 4) * 32 + lane];

            const int   kb = wbase + k * 128 + 4 * lane + 1 + T;  // idx+1+T >= T+1
            const float r0 = __fdividef(1.0f, (float)kb);         // one RCP / 4 elems
            float kr[4];
            kr[0] = K2F * r0;                                     // folds 2*log2e/tau
#pragma unroll
            for (int j = 1; j < 4; j++) {
                const float tj = (float)j * r0;                   // Taylor 1/(kb+j)
                kr[j] = kr[0] * __fmaf_rn(tj, tj, 1.0f - tj);
            }
            float cf = (float)(wgb + cfstart[k]);
            const float q[4] = {p.x, p.y, p.z, p.w};
#pragma unroll
            for (int j = 0; j < 4; j++) {
                const unsigned b = (bits >> (4 * k + j)) & 1u;
                cf += b ? 1.0f : 0.0f;
                const float f  = cf * kr[j];                      // 0 when c==0
                const float e  = ex2f(f);
                const float df = f - __log2f(q[j]);
                S += e;
                W = __fmaf_rn(e, df, W);
            }
        }

        // ---- warpgroup reduce (S, W) ----
#pragma unroll
        for (int d = 16; d; d >>= 1) {
            S += __shfl_down_sync(0xffffffffu, S, d);
            W += __shfl_down_sync(0xffffffffu, W, d);
        }
        if (lane == 0) { s_S[warp] = S; s_W[warp] = W; }
        asm volatile("bar.sync %0, %1;" :: "r"(barid), "r"(128) : "memory");
        if (wwin == 0 && lane == 0) {
            const float St = s_S[wg*4+0] + s_S[wg*4+1] + s_S[wg*4+2] + s_S[wg*4+3];
            const float Wt = s_W[wg*4+0] + s_W[wg*4+1] + s_W[wg*4+2] + s_W[wg*4+3];
            const float rv = LN2F * (Wt / St) - __logf(St);       // ln2*(W/S) - ln(S)
            // deterministic fixed-point accumulation (integer adds commute)
            const long long q32 = __float2ll_rn((double)rv * FIXSCALE);
            atomicAdd(&g_acc, (unsigned long long)q32);
        }
    }

    // ---- ticket: last CTA converts & resets (no gather tail) ----
    __syncthreads();
    if (t == 0) {
        __threadfence();
        unsigned ticket = atomicInc(&g_count, GRID - 1);          // wraps after GRID
        if (ticket == GRID - 1) {
            __threadfence();
            const long long v = (long long)g_acc;
            d_out[0] = (float)((double)v * (1.0 / FIXSCALE) / (double)NB);
            g_acc = 0;                                            // reset for next replay
        }
    }
}

extern "C" void kernel_launch(void* const* d_in, const int* in_sizes, int n_in,
                              void* d_out, int out_size) {
    const float* probs  = (const float*)d_in[0];   // output: (B, L, 1) f32
    const int*   labels = (const int*)d_in[1];     // labels: (B, L) i32
    fused_kernel<<<GRID, NT>>>(probs, labels, (float*)d_out);
}